// round 1
// baseline (speedup 1.0000x reference)
#include <cuda_runtime.h>
#include <cstdint>

// Problem constants
#define NN 1024   // nodes (N)
#define NB 8      // batch
#define NS 64     // timesteps
#define NH 32     // hidden

// GEMM tiling
#define BM 128
#define BN 256
#define BK 32
#define THREADS 256
#define KITERS (NN / BK)   // 32

// SMEM pitches (floats)
#define APITCH 40   // 128x32 A tile rows padded: 16B-aligned rows, mild 2-way frag conflict
#define BPITCH 264  // 32x256 B tile rows padded: conflict-free B-frag loads
#define ZPITCH 257  // epilogue Z tile: conflict-free per-thread column walks

#define SMEM_STAGE_FLOATS (2 * BM * APITCH + 2 * BK * BPITCH)   // 27136
#define SMEM_Z_FLOATS     (BM * ZPITCH)                          // 32896
#define SMEM_BYTES        (SMEM_Z_FLOATS * 4)                    // 131584 > staging

// Hidden state scratch: h[b][n][u]
__device__ float g_h[NB * NN * NH];

__device__ __forceinline__ uint32_t f2tf(float f) {
    uint32_t u;
    asm("cvt.rna.tf32.f32 %0, %1;" : "=r"(u) : "f"(f));
    return u;
}

__device__ __forceinline__ void mma_tf32(float c[4], const uint32_t a[4], const uint32_t b[2]) {
    asm volatile(
        "mma.sync.aligned.m16n8k8.row.col.f32.tf32.tf32.f32 "
        "{%0,%1,%2,%3}, {%4,%5,%6,%7}, {%8,%9}, {%0,%1,%2,%3};\n"
        : "+f"(c[0]), "+f"(c[1]), "+f"(c[2]), "+f"(c[3])
        : "r"(a[0]), "r"(a[1]), "r"(a[2]), "r"(a[3]), "r"(b[0]), "r"(b[1]));
}

// Fused kernel: per (b, n-tile of 128, u-pair) computes
//   Z[n, (u_l, t, gate)] = sum_m G[b,n,m] * (W_gate[u,m] * x[b,m,t])
// then runs the GRU recurrence over t in the epilogue and writes h[b,n,u].
__global__ void __launch_bounds__(THREADS, 1)
gate_gemm_kernel(const float* __restrict__ G,   // (B, N, N)
                 const float* __restrict__ X,   // (B, N, S) [C_IN=1]
                 const float* __restrict__ Wu,  // (H, N)
                 const float* __restrict__ bu,  // (H)
                 const float* __restrict__ Wc,  // (H, N)
                 const float* __restrict__ bc,  // (H)
                 const float* __restrict__ h0)  // (H, N)
{
    extern __shared__ float smem[];
    float* As = smem;                      // [2][BM][APITCH]
    float* Bs = smem + 2 * BM * APITCH;    // [2][BK][BPITCH]

    const int tid  = threadIdx.x;
    const int lane = tid & 31;
    const int wid  = tid >> 5;
    const int wm   = wid >> 2;     // 0..1 : 64-row slab
    const int wn   = wid & 3;      // 0..3 : 64-col slab
    const int grp  = lane >> 2;    // 0..7
    const int qid  = lane & 3;     // 0..3

    const int n0 = blockIdx.x * BM;
    const int u0 = blockIdx.y * 2;
    const int b  = blockIdx.z;

    const float* gA = G + ((size_t)b * NN + n0) * NN;

    // B-staging assignment: thread owns k-row (tid>>3), 32 consecutive cols
    const int bk   = tid >> 3;             // 0..31
    const int bc0  = (tid & 7) * 32;       // 0,32,...,224
    const int b_ul = bc0 >> 7;             // u_local (0/1)
    const int b_t0 = (bc0 & 127) >> 1;     // first t of this 16-t segment
    const float* wu_row = Wu + (size_t)(u0 + b_ul) * NN;
    const float* wc_row = Wc + (size_t)(u0 + b_ul) * NN;
    const float* xb     = X + (size_t)b * NN * NS;

    float acc[4][8][4];
#pragma unroll
    for (int i = 0; i < 4; i++)
#pragma unroll
        for (int j = 0; j < 8; j++)
#pragma unroll
            for (int r = 0; r < 4; r++) acc[i][j][r] = 0.f;

    float4 pa[4];
    float4 px[4];
    float  pwu, pwc;

#define PREFETCH(k0) do {                                                          \
    _Pragma("unroll")                                                              \
    for (int i = 0; i < 4; i++) {                                                  \
        int q = tid + i * 256;                                                     \
        pa[i] = *reinterpret_cast<const float4*>(                                  \
            gA + (size_t)(q >> 3) * NN + (k0) + (q & 7) * 4);                      \
    }                                                                              \
    {                                                                              \
        int m = (k0) + bk;                                                         \
        pwu = wu_row[m];                                                           \
        pwc = wc_row[m];                                                           \
        const float* xr = xb + (size_t)m * NS + b_t0;                              \
        _Pragma("unroll")                                                          \
        for (int j = 0; j < 4; j++)                                                \
            px[j] = *reinterpret_cast<const float4*>(xr + j * 4);                  \
    }                                                                              \
} while (0)

#define STAGE(bufi) do {                                                           \
    float* Ad = As + (bufi) * BM * APITCH;                                         \
    _Pragma("unroll")                                                              \
    for (int i = 0; i < 4; i++) {                                                  \
        int q = tid + i * 256;                                                     \
        uint4 v;                                                                   \
        v.x = f2tf(pa[i].x); v.y = f2tf(pa[i].y);                                  \
        v.z = f2tf(pa[i].z); v.w = f2tf(pa[i].w);                                  \
        *reinterpret_cast<uint4*>(Ad + (q >> 3) * APITCH + (q & 7) * 4) = v;       \
    }                                                                              \
    {                                                                              \
        float* Bd = Bs + (bufi) * BK * BPITCH + bk * BPITCH + bc0;                 \
        _Pragma("unroll")                                                          \
        for (int j = 0; j < 4; j++) {                                              \
            uint4 v0, v1;                                                          \
            v0.x = f2tf(pwu * px[j].x); v0.y = f2tf(pwc * px[j].x);                \
            v0.z = f2tf(pwu * px[j].y); v0.w = f2tf(pwc * px[j].y);                \
            v1.x = f2tf(pwu * px[j].z); v1.y = f2tf(pwc * px[j].z);                \
            v1.z = f2tf(pwu * px[j].w); v1.w = f2tf(pwc * px[j].w);                \
            *reinterpret_cast<uint4*>(Bd + j * 8)     = v0;                        \
            *reinterpret_cast<uint4*>(Bd + j * 8 + 4) = v1;                        \
        }                                                                          \
    }                                                                              \
} while (0)

#define COMPUTE(bufi) do {                                                         \
    const float* Ab = As + (bufi) * BM * APITCH + (wm * 64) * APITCH;              \
    const float* Bb = Bs + (bufi) * BK * BPITCH;                                   \
    _Pragma("unroll")                                                              \
    for (int ks = 0; ks < 4; ks++) {                                               \
        uint32_t af[4][4], bf[8][2];                                               \
        _Pragma("unroll")                                                          \
        for (int mi = 0; mi < 4; mi++) {                                           \
            const float* ap = Ab + (mi * 16 + grp) * APITCH + ks * 8 + qid;        \
            af[mi][0] = __float_as_uint(ap[0]);                                    \
            af[mi][1] = __float_as_uint(ap[8 * APITCH]);                           \
            af[mi][2] = __float_as_uint(ap[4]);                                    \
            af[mi][3] = __float_as_uint(ap[8 * APITCH + 4]);                       \
        }                                                                          \
        _Pragma("unroll")                                                          \
        for (int nj = 0; nj < 8; nj++) {                                           \
            const float* bp = Bb + (ks * 8 + qid) * BPITCH + wn * 64 + nj * 8 + grp; \
            bf[nj][0] = __float_as_uint(bp[0]);                                    \
            bf[nj][1] = __float_as_uint(bp[4 * BPITCH]);                           \
        }                                                                          \
        _Pragma("unroll")                                                          \
        for (int mi = 0; mi < 4; mi++)                                             \
        _Pragma("unroll")                                                          \
        for (int nj = 0; nj < 8; nj++)                                             \
            mma_tf32(acc[mi][nj], af[mi], bf[nj]);                                 \
    }                                                                              \
} while (0)

    PREFETCH(0);
    STAGE(0);
    __syncthreads();

#pragma unroll 1
    for (int kt = 0; kt < KITERS; kt++) {
        if (kt + 1 < KITERS) PREFETCH((kt + 1) * BK);
        COMPUTE(kt & 1);
        if (kt + 1 < KITERS) {
            STAGE((kt + 1) & 1);
            __syncthreads();
        }
    }

    // ---- Epilogue: dump Z to SMEM, run the GRU recurrence over t ----
    __syncthreads();   // all MMA reads of staging smem done; safe to alias
    float* Zs = smem;  // [BM][ZPITCH]
#pragma unroll
    for (int mi = 0; mi < 4; mi++)
#pragma unroll
        for (int nj = 0; nj < 8; nj++)
#pragma unroll
            for (int r = 0; r < 4; r++) {
                int row = wm * 64 + mi * 16 + grp + ((r >> 1) ? 8 : 0);
                int col = wn * 64 + nj * 8 + qid * 2 + (r & 1);
                Zs[row * ZPITCH + col] = acc[mi][nj][r];
            }
    __syncthreads();

    {
        const int row = tid & 127;
        const int ul  = tid >> 7;
        const int n   = n0 + row;
        const int u   = u0 + ul;
        float h    = h0[(size_t)u * NN + n];
        const float bu_v = bu[u];
        const float bc_v = bc[u];
        const float* zrow = Zs + row * ZPITCH + ul * 128;
#pragma unroll 1
        for (int t = 0; t < NS; t++) {
            float zu = zrow[2 * t]     + bu_v;
            float zc = zrow[2 * t + 1] + bc_v;
            float ug = 1.f / (1.f + __expf(-zu));
            float cg = tanhf(zc);
            h = fmaf(ug, h - cg, cg);   // ug*h + (1-ug)*cg
        }
        g_h[((size_t)b * NN + n) * NH + u] = h;
    }

#undef PREFETCH
#undef STAGE
#undef COMPUTE
}

// Prediction head: one warp per (b, n). lane = hidden channel u.
__global__ void head_kernel(const float* __restrict__ W1, const float* __restrict__ b1,
                            const float* __restrict__ W2, const float* __restrict__ b2,
                            const float* __restrict__ Wd, const float* __restrict__ bd,
                            float* __restrict__ out)
{
    const int warp = (blockIdx.x * blockDim.x + threadIdx.x) >> 5;
    const int lane = threadIdx.x & 31;
    if (warp >= NB * NN) return;
    const int b = warp >> 10;
    const int n = warp & (NN - 1);

    const float hv = g_h[((size_t)b * NN + n) * NH + lane];

    float x1 = b1[lane];
    const float* w1r = W1 + lane * NH;
#pragma unroll
    for (int k = 0; k < NH; k++)
        x1 = fmaf(w1r[k], __shfl_sync(0xffffffffu, hv, k), x1);
    x1 = x1 >= 0.f ? x1 : 0.01f * x1;   // leaky_relu default slope

    float x2 = b2[lane];
    const float* w2r = W2 + lane * 2 * NH;
#pragma unroll
    for (int k = 0; k < NH; k++)
        x2 = fmaf(w2r[k], __shfl_sync(0xffffffffu, x1, k), x2);
#pragma unroll
    for (int k = 0; k < NH; k++)
        x2 = fmaf(w2r[NH + k], __shfl_sync(0xffffffffu, hv, k), x2);
    x2 = x2 >= 0.f ? x2 : 0.01f * x2;

    // dec_in = [x2; h]; out = Wd[n,0,:] . dec_in + bd[n]
    float v = Wd[(size_t)n * 2 * NH + lane] * x2
            + Wd[(size_t)n * 2 * NH + NH + lane] * hv;
#pragma unroll
    for (int o = 16; o; o >>= 1) v += __shfl_xor_sync(0xffffffffu, v, o);
    if (lane == 0) out[(size_t)b * NN + n] = v + bd[n];
}

extern "C" void kernel_launch(void* const* d_in, const int* in_sizes, int n_in,
                              void* d_out, int out_size)
{
    (void)in_sizes; (void)n_in; (void)out_size;
    const float* x  = (const float*)d_in[0];
    // d_in[1] = mask (unused by the module)
    const float* g  = (const float*)d_in[2];
    // d_in[3], d_in[4] = Wf, bf (mathematically irrelevant: r-gate has no effect)
    const float* Wu = (const float*)d_in[5];
    const float* bu = (const float*)d_in[6];
    const float* Wc = (const float*)d_in[7];
    const float* bc = (const float*)d_in[8];
    const float* h0 = (const float*)d_in[9];
    const float* W1 = (const float*)d_in[10];
    const float* b1 = (const float*)d_in[11];
    const float* W2 = (const float*)d_in[12];
    const float* b2 = (const float*)d_in[13];
    const float* Wd = (const float*)d_in[14];
    const float* bd = (const float*)d_in[15];
    float* out = (float*)d_out;

    cudaFuncSetAttribute(gate_gemm_kernel,
                         cudaFuncAttributeMaxDynamicSharedMemorySize, SMEM_BYTES);

    dim3 grid(NN / BM, NH / 2, NB);   // (8, 16, 8) = 1024 CTAs
    gate_gemm_kernel<<<grid, THREADS, SMEM_BYTES>>>(g, x, Wu, bu, Wc, bc, h0);

    head_kernel<<<(NB * NN) / 8, 256>>>(W1, b1, W2, b2, Wd, bd, out);
}

// round 2
// speedup vs baseline: 1.1531x; 1.1531x over previous
#include <cuda_runtime.h>
#include <cstdint>

// Problem constants
#define NN 1024   // nodes (N)
#define NB 8      // batch
#define NS 64     // timesteps
#define NH 32     // hidden

// GEMM tiling
#define BM 128
#define BN 256
#define BK 32
#define THREADS 256
#define KITERS (NN / BK)   // 32

// SMEM pitches (floats)
#define APITCH 36   // 36 % 32 == 4 -> A-frag lane banks (grp*4+qid) all distinct: conflict-free
#define BPITCH 264  // conflict-free B-frag loads
#define ZPITCH 257  // epilogue Z tile: conflict-free per-thread column walks

#define SMEM_STAGE_FLOATS (2 * BM * APITCH + 2 * BK * BPITCH)
#define SMEM_Z_FLOATS     (BM * ZPITCH)
#define SMEM_BYTES        (SMEM_Z_FLOATS * 4)   // Z (131584 B) > staging

// Hidden state scratch: h[b][n][u]
__device__ float g_h[NB * NN * NH];

__device__ __forceinline__ uint32_t f2tf(float f) {
    uint32_t u;
    asm("cvt.rna.tf32.f32 %0, %1;" : "=r"(u) : "f"(f));
    return u;
}

__device__ __forceinline__ void mma_tf32(float c[4], const uint32_t a[4], const uint32_t b[2]) {
    asm volatile(
        "mma.sync.aligned.m16n8k8.row.col.f32.tf32.tf32.f32 "
        "{%0,%1,%2,%3}, {%4,%5,%6,%7}, {%8,%9}, {%0,%1,%2,%3};\n"
        : "+f"(c[0]), "+f"(c[1]), "+f"(c[2]), "+f"(c[3])
        : "r"(a[0]), "r"(a[1]), "r"(a[2]), "r"(a[3]), "r"(b[0]), "r"(b[1]));
}

// Fused kernel: per (b, n-tile of 128, u-pair) computes
//   Z[n, (u_l, t, gate)] = sum_m G[b,n,m] * (W_gate[u,m] * x[b,m,t])
// then runs the GRU recurrence over t in the epilogue and writes h[b,n,u].
__global__ void __launch_bounds__(THREADS, 1)
gate_gemm_kernel(const float* __restrict__ G,   // (B, N, N)
                 const float* __restrict__ X,   // (B, N, S) [C_IN=1]
                 const float* __restrict__ Wu,  // (H, N)
                 const float* __restrict__ bu,  // (H)
                 const float* __restrict__ Wc,  // (H, N)
                 const float* __restrict__ bc,  // (H)
                 const float* __restrict__ h0)  // (H, N)
{
    extern __shared__ float smem[];
    float* As = smem;                      // [2][BM][APITCH]
    float* Bs = smem + 2 * BM * APITCH;    // [2][BK][BPITCH]

    const int tid  = threadIdx.x;
    const int lane = tid & 31;
    const int wid  = tid >> 5;
    const int wm   = wid >> 2;     // 0..1 : 64-row slab
    const int wn   = wid & 3;      // 0..3 : 64-col slab
    const int grp  = lane >> 2;    // 0..7
    const int qid  = lane & 3;     // 0..3

    const int n0 = blockIdx.x * BM;
    const int u0 = blockIdx.y * 2;
    const int b  = blockIdx.z;

    const float* gA = G + ((size_t)b * NN + n0) * NN;

    // B-staging assignment: thread owns k-row (tid>>3), 32 consecutive cols
    const int bk   = tid >> 3;             // 0..31
    const int bc0  = (tid & 7) * 32;       // 0,32,...,224
    const int b_ul = bc0 >> 7;             // u_local (0/1)
    const int b_t0 = (bc0 & 127) >> 1;     // first t of this 16-t segment
    const float* wu_row = Wu + (size_t)(u0 + b_ul) * NN;
    const float* wc_row = Wc + (size_t)(u0 + b_ul) * NN;
    const float* xb     = X + (size_t)b * NN * NS;

    float acc[4][8][4];
#pragma unroll
    for (int i = 0; i < 4; i++)
#pragma unroll
        for (int j = 0; j < 8; j++)
#pragma unroll
            for (int r = 0; r < 4; r++) acc[i][j][r] = 0.f;

    float4 pa[4];
    float4 px[4];
    float  pwu, pwc;

#define PREFETCH(k0) do {                                                          \
    _Pragma("unroll")                                                              \
    for (int i = 0; i < 4; i++) {                                                  \
        int q = tid + i * 256;                                                     \
        pa[i] = *reinterpret_cast<const float4*>(                                  \
            gA + (size_t)(q >> 3) * NN + (k0) + (q & 7) * 4);                      \
    }                                                                              \
    {                                                                              \
        int m = (k0) + bk;                                                         \
        pwu = wu_row[m];                                                           \
        pwc = wc_row[m];                                                           \
        const float* xr = xb + (size_t)m * NS + b_t0;                              \
        _Pragma("unroll")                                                          \
        for (int j = 0; j < 4; j++)                                                \
            px[j] = *reinterpret_cast<const float4*>(xr + j * 4);                  \
    }                                                                              \
} while (0)

#define STAGE(bufi) do {                                                           \
    float* Ad = As + (bufi) * BM * APITCH;                                         \
    _Pragma("unroll")                                                              \
    for (int i = 0; i < 4; i++) {                                                  \
        int q = tid + i * 256;                                                     \
        uint4 v;                                                                   \
        v.x = f2tf(pa[i].x); v.y = f2tf(pa[i].y);                                  \
        v.z = f2tf(pa[i].z); v.w = f2tf(pa[i].w);                                  \
        *reinterpret_cast<uint4*>(Ad + (q >> 3) * APITCH + (q & 7) * 4) = v;       \
    }                                                                              \
    {                                                                              \
        float* Bd = Bs + (bufi) * BK * BPITCH + bk * BPITCH + bc0;                 \
        _Pragma("unroll")                                                          \
        for (int j = 0; j < 4; j++) {                                              \
            uint4 v0, v1;                                                          \
            v0.x = f2tf(pwu * px[j].x); v0.y = f2tf(pwc * px[j].x);                \
            v0.z = f2tf(pwu * px[j].y); v0.w = f2tf(pwc * px[j].y);                \
            v1.x = f2tf(pwu * px[j].z); v1.y = f2tf(pwc * px[j].z);                \
            v1.z = f2tf(pwu * px[j].w); v1.w = f2tf(pwc * px[j].w);                \
            *reinterpret_cast<uint4*>(Bd + j * 8)     = v0;                        \
            *reinterpret_cast<uint4*>(Bd + j * 8 + 4) = v1;                        \
        }                                                                          \
    }                                                                              \
} while (0)

#define COMPUTE(bufi) do {                                                         \
    const float* Ab = As + (bufi) * BM * APITCH + (wm * 64) * APITCH;              \
    const float* Bb = Bs + (bufi) * BK * BPITCH;                                   \
    _Pragma("unroll")                                                              \
    for (int ks = 0; ks < 4; ks++) {                                               \
        uint32_t af[4][4], bf[8][2];                                               \
        _Pragma("unroll")                                                          \
        for (int mi = 0; mi < 4; mi++) {                                           \
            const float* ap = Ab + (mi * 16 + grp) * APITCH + ks * 8 + qid;        \
            af[mi][0] = __float_as_uint(ap[0]);                                    \
            af[mi][1] = __float_as_uint(ap[8 * APITCH]);                           \
            af[mi][2] = __float_as_uint(ap[4]);                                    \
            af[mi][3] = __float_as_uint(ap[8 * APITCH + 4]);                       \
        }                                                                          \
        _Pragma("unroll")                                                          \
        for (int nj = 0; nj < 8; nj++) {                                           \
            const float* bp = Bb + (ks * 8 + qid) * BPITCH + wn * 64 + nj * 8 + grp; \
            bf[nj][0] = __float_as_uint(bp[0]);                                    \
            bf[nj][1] = __float_as_uint(bp[4 * BPITCH]);                           \
        }                                                                          \
        _Pragma("unroll")                                                          \
        for (int mi = 0; mi < 4; mi++)                                             \
        _Pragma("unroll")                                                          \
        for (int nj = 0; nj < 8; nj++)                                             \
            mma_tf32(acc[mi][nj], af[mi], bf[nj]);                                 \
    }                                                                              \
} while (0)

    PREFETCH(0);
    STAGE(0);
    __syncthreads();

#pragma unroll 1
    for (int kt = 0; kt < KITERS; kt++) {
        if (kt + 1 < KITERS) PREFETCH((kt + 1) * BK);
        COMPUTE(kt & 1);
        if (kt + 1 < KITERS) {
            STAGE((kt + 1) & 1);
            __syncthreads();
        }
    }

    // ---- Epilogue: dump Z to SMEM, run the GRU recurrence over t ----
    __syncthreads();   // all MMA reads of staging smem done; safe to alias
    float* Zs = smem;  // [BM][ZPITCH]
#pragma unroll
    for (int mi = 0; mi < 4; mi++)
#pragma unroll
        for (int nj = 0; nj < 8; nj++)
#pragma unroll
            for (int r = 0; r < 4; r++) {
                int row = wm * 64 + mi * 16 + grp + ((r >> 1) ? 8 : 0);
                int col = wn * 64 + nj * 8 + qid * 2 + (r & 1);
                Zs[row * ZPITCH + col] = acc[mi][nj][r];
            }
    __syncthreads();

    {
        const int row = tid & 127;
        const int ul  = tid >> 7;
        const int n   = n0 + row;
        const int u   = u0 + ul;
        float h    = h0[(size_t)u * NN + n];
        const float bu_v = bu[u];
        const float bc_v = bc[u];
        const float* zrow = Zs + row * ZPITCH + ul * 128;
#pragma unroll 1
        for (int t = 0; t < NS; t++) {
            float zu = zrow[2 * t]     + bu_v;
            float zc = zrow[2 * t + 1] + bc_v;
            float ug = 1.f / (1.f + __expf(-zu));
            float cg = tanhf(zc);
            h = fmaf(ug, h - cg, cg);   // ug*h + (1-ug)*cg
        }
        g_h[((size_t)b * NN + n) * NH + u] = h;
    }

#undef PREFETCH
#undef STAGE
#undef COMPUTE
}

// Prediction head: one warp per (b, n). lane = hidden channel u.
// W1/W2 staged TRANSPOSED in smem (pad 33) so per-k reads are conflict-free
// single-wavefront LDS instead of 32-line strided LDG (the 90us bug in R1).
#define W1T_PITCH 33
__global__ void __launch_bounds__(256)
head_kernel(const float* __restrict__ W1, const float* __restrict__ b1,
            const float* __restrict__ W2, const float* __restrict__ b2,
            const float* __restrict__ Wd, const float* __restrict__ bd,
            float* __restrict__ out)
{
    __shared__ float w1t[NH * W1T_PITCH];        // w1t[k][u] = W1[u][k]
    __shared__ float w2t[2 * NH * W1T_PITCH];    // w2t[k][u] = W2[u][k]
    __shared__ float b1s[NH], b2s[NH];

    const int tid = threadIdx.x;
    // Stage weights (coalesced global reads; padded smem writes conflict-free)
    for (int i = tid; i < NH * NH; i += 256) {
        int u = i >> 5, k = i & 31;
        w1t[k * W1T_PITCH + u] = W1[i];
    }
    for (int i = tid; i < NH * 2 * NH; i += 256) {
        int u = i >> 6, k = i & 63;
        w2t[k * W1T_PITCH + u] = W2[i];
    }
    if (tid < NH) { b1s[tid] = b1[tid]; b2s[tid] = b2[tid]; }
    __syncthreads();

    const int warp = (blockIdx.x * blockDim.x + tid) >> 5;
    const int lane = tid & 31;
    if (warp >= NB * NN) return;
    const int b = warp >> 10;
    const int n = warp & (NN - 1);

    const float hv = g_h[((size_t)b * NN + n) * NH + lane];

    float x1 = b1s[lane];
#pragma unroll
    for (int k = 0; k < NH; k++)
        x1 = fmaf(w1t[k * W1T_PITCH + lane], __shfl_sync(0xffffffffu, hv, k), x1);
    x1 = x1 >= 0.f ? x1 : 0.01f * x1;   // leaky_relu default slope

    float x2 = b2s[lane];
#pragma unroll
    for (int k = 0; k < NH; k++)
        x2 = fmaf(w2t[k * W1T_PITCH + lane], __shfl_sync(0xffffffffu, x1, k), x2);
#pragma unroll
    for (int k = 0; k < NH; k++)
        x2 = fmaf(w2t[(NH + k) * W1T_PITCH + lane], __shfl_sync(0xffffffffu, hv, k), x2);
    x2 = x2 >= 0.f ? x2 : 0.01f * x2;

    // dec_in = [x2; h]; out = Wd[n,0,:] . dec_in + bd[n]
    float v = Wd[(size_t)n * 2 * NH + lane] * x2
            + Wd[(size_t)n * 2 * NH + NH + lane] * hv;
#pragma unroll
    for (int o = 16; o; o >>= 1) v += __shfl_xor_sync(0xffffffffu, v, o);
    if (lane == 0) out[(size_t)b * NN + n] = v + bd[n];
}

extern "C" void kernel_launch(void* const* d_in, const int* in_sizes, int n_in,
                              void* d_out, int out_size)
{
    (void)in_sizes; (void)n_in; (void)out_size;
    const float* x  = (const float*)d_in[0];
    // d_in[1] = mask (unused by the module)
    const float* g  = (const float*)d_in[2];
    // d_in[3], d_in[4] = Wf, bf (mathematically irrelevant: r-gate has no effect)
    const float* Wu = (const float*)d_in[5];
    const float* bu = (const float*)d_in[6];
    const float* Wc = (const float*)d_in[7];
    const float* bc = (const float*)d_in[8];
    const float* h0 = (const float*)d_in[9];
    const float* W1 = (const float*)d_in[10];
    const float* b1 = (const float*)d_in[11];
    const float* W2 = (const float*)d_in[12];
    const float* b2 = (const float*)d_in[13];
    const float* Wd = (const float*)d_in[14];
    const float* bd = (const float*)d_in[15];
    float* out = (float*)d_out;

    cudaFuncSetAttribute(gate_gemm_kernel,
                         cudaFuncAttributeMaxDynamicSharedMemorySize, SMEM_BYTES);

    dim3 grid(NN / BM, NH / 2, NB);   // (8, 16, 8) = 1024 CTAs
    gate_gemm_kernel<<<grid, THREADS, SMEM_BYTES>>>(g, x, Wu, bu, Wc, bc, h0);

    head_kernel<<<(NB * NN) / 8, 256>>>(W1, b1, W2, b2, Wd, bd, out);
}

// round 4
// speedup vs baseline: 2.2371x; 1.9401x over previous
#include <cuda_runtime.h>
#include <cuda_fp16.h>
#include <cstdint>

// Problem constants
#define NN 1024   // nodes
#define NB 8      // batch
#define NS 64     // timesteps
#define NH 32     // hidden

// GEMM tiling: per CTA, M=128 (n rows) x N=256 cols (2u x 64t x 2 gates), K=1024
#define BK 64
#define NKT 16           // k-iters
#define AP 80            // halfs per A row (64 data + 16 pad) -> conflict-free LDS.64
#define BP 80            // halfs per B col
#define ACHUNK (128 * AP)   // 10240 halfs per (tile, kchunk)
#define BCHUNK (256 * BP)   // 20480
#define ABYTES (ACHUNK * 2) // 20480 B
#define BBYTES (BCHUNK * 2) // 40960 B
#define ZPITCH 257
#define SMEM_BYTES (128 * ZPITCH * 4)   // 131584; staging (122880) aliases this

// Precomputed operand buffers (fragment-permuted, padded layouts)
__device__ __half g_A[(size_t)NB * 8 * NKT * ACHUNK];    // ~21 MB
__device__ __half g_B[(size_t)NB * 16 * NKT * BCHUNK];   // ~84 MB
__device__ float  g_h[NB * NN * NH];

// ---------------- helpers ----------------
__device__ __forceinline__ uint32_t smem_u32(const void* p) {
    uint32_t a;
    asm("{ .reg .u64 t; cvta.to.shared.u64 t, %1; cvt.u32.u64 %0, t; }" : "=r"(a) : "l"(p));
    return a;
}
__device__ __forceinline__ void cp16(uint32_t s, const void* g) {
    asm volatile("cp.async.cg.shared.global [%0], [%1], 16;" :: "r"(s), "l"(g) : "memory");
}
__device__ __forceinline__ void cp_commit() {
    asm volatile("cp.async.commit_group;" ::: "memory");
}
template <int N>
__device__ __forceinline__ void cp_wait() {
    asm volatile("cp.async.wait_group %0;" :: "n"(N) : "memory");
}
__device__ __forceinline__ void mma_f16(float c[4], uint2 alo, uint2 ahi, uint2 bf) {
    asm volatile(
        "mma.sync.aligned.m16n8k16.row.col.f32.f16.f16.f32 "
        "{%0,%1,%2,%3}, {%4,%5,%6,%7}, {%8,%9}, {%0,%1,%2,%3};\n"
        : "+f"(c[0]), "+f"(c[1]), "+f"(c[2]), "+f"(c[3])
        : "r"(alo.x), "r"(ahi.x), "r"(alo.y), "r"(ahi.y), "r"(bf.x), "r"(bf.y));
}
__device__ __forceinline__ uint32_t pack2(float a, float b) {
    __half2 h = __halves2half2(__float2half_rn(a), __float2half_rn(b));
    return *reinterpret_cast<uint32_t*>(&h);
}

// ---------------- prep: A = half(G), fragment-permuted ----------------
// g_A[((b*8+mt)*16+kt)*ACHUNK + row*AP + ks*16 + q*4 + s], s -> k = 2q+(s&1)+((s>>1)<<3)
__global__ void convA_kernel(const float* __restrict__ G) {
    int idx = blockIdx.x * 256 + threadIdx.x;   // 2,097,152 quads
    int q   = idx & 3;
    int ks  = (idx >> 2) & 3;
    int row = (idx >> 4) & 127;
    int kt  = (idx >> 11) & 15;
    int mt  = (idx >> 15) & 7;
    int b   = idx >> 18;
    const float* src = G + ((size_t)b * NN + mt * 128 + row) * NN + kt * 64 + ks * 16 + 2 * q;
    uint2 v;
    v.x = pack2(src[0], src[1]);
    v.y = pack2(src[8], src[9]);
    *reinterpret_cast<uint2*>(
        g_A + (size_t)((b * 8 + mt) * 16 + kt) * ACHUNK + row * AP + ks * 16 + q * 4) = v;
}

// ---------------- prep: B[col,m] = half(W_g[u,m] * x[b,m,t]), permuted ----------------
// col = ul*128 + t*2 + gate;  g_B[((b*16+nt)*16+kt)*BCHUNK + col*BP + ks*16 + q*4 + s]
__global__ void convB_kernel(const float* __restrict__ X,
                             const float* __restrict__ Wu,
                             const float* __restrict__ Wc) {
    int idx = blockIdx.x * 256 + threadIdx.x;   // 8,388,608 quads
    int q   = idx & 3;
    int ks  = (idx >> 2) & 3;
    int col = (idx >> 4) & 255;
    int kt  = (idx >> 12) & 15;
    int nt  = (idx >> 16) & 15;
    int b   = idx >> 20;
    int ul = col >> 7, t = (col & 127) >> 1, gate = col & 1;
    int u  = nt * 2 + ul;
    int k0 = kt * 64 + ks * 16 + 2 * q;
    const float* W  = (gate ? Wc : Wu) + (size_t)u * NN + k0;
    const float* xb = X + (size_t)b * NN * NS + (size_t)k0 * NS + t;
    uint2 v;
    v.x = pack2(W[0] * xb[0],      W[1] * xb[NS]);
    v.y = pack2(W[8] * xb[8 * NS], W[9] * xb[9 * NS]);
    *reinterpret_cast<uint2*>(
        g_B + (size_t)((b * 16 + nt) * 16 + kt) * BCHUNK + col * BP + ks * 16 + q * 4) = v;
}

// ---------------- main: fp16 HMMA GEMM + fused GRU scan ----------------
__global__ void __launch_bounds__(256, 1)
gemm_gru_kernel(const float* __restrict__ bu, const float* __restrict__ bc,
                const float* __restrict__ h0)
{
    extern __shared__ __align__(16) char smem[];
    const uint32_t sb = smem_u32(smem);

    const int tid  = threadIdx.x;
    const int wid  = tid >> 5;
    const int lane = tid & 31;
    const int wm   = wid >> 2;    // 0..1
    const int wn   = wid & 3;     // 0..3
    const int grp  = lane >> 2;   // 0..7
    const int qid  = lane & 3;    // 0..3

    const int mt = blockIdx.x;    // n-tile (8)
    const int nt = blockIdx.y;    // u-pair (16)
    const int b  = blockIdx.z;

    const __half* Asrc = g_A + (size_t)((b * 8 + mt) * 16) * ACHUNK;
    const __half* Bsrc = g_B + (size_t)((b * 16 + nt) * 16) * BCHUNK;

    float acc[4][8][4];
#pragma unroll
    for (int i = 0; i < 4; i++)
#pragma unroll
        for (int j = 0; j < 8; j++)
#pragma unroll
            for (int r = 0; r < 4; r++) acc[i][j][r] = 0.f;

#define ISSUE(KT, BUF) do {                                                        \
    uint32_t sa = sb + (BUF) * ABYTES;                                             \
    const char* ga = (const char*)(Asrc + (size_t)(KT) * ACHUNK);                  \
    _Pragma("unroll")                                                              \
    for (int i = 0; i < 5; i++)                                                    \
        cp16(sa + tid * 16 + i * 4096, ga + tid * 16 + i * 4096);                  \
    uint32_t sB = sb + 2 * ABYTES + (BUF) * BBYTES;                                \
    const char* gb = (const char*)(Bsrc + (size_t)(KT) * BCHUNK);                  \
    _Pragma("unroll")                                                              \
    for (int i = 0; i < 10; i++)                                                   \
        cp16(sB + tid * 16 + i * 4096, gb + tid * 16 + i * 4096);                  \
    cp_commit();                                                                   \
} while (0)

#define COMPUTE(BUF) do {                                                          \
    const __half* Ab = (const __half*)(smem + (BUF) * ABYTES);                     \
    const __half* Bb = (const __half*)(smem + 2 * ABYTES + (BUF) * BBYTES);        \
    _Pragma("unroll")                                                              \
    for (int ks = 0; ks < 4; ks++) {                                               \
        uint2 alo[4], ahi[4], bf[8];                                               \
        _Pragma("unroll")                                                          \
        for (int mi = 0; mi < 4; mi++) {                                           \
            const __half* ap = Ab + (wm * 64 + mi * 16 + grp) * AP + ks * 16 + qid * 4; \
            alo[mi] = *reinterpret_cast<const uint2*>(ap);                         \
            ahi[mi] = *reinterpret_cast<const uint2*>(ap + 8 * AP);                \
        }                                                                          \
        _Pragma("unroll")                                                          \
        for (int nj = 0; nj < 8; nj++)                                             \
            bf[nj] = *reinterpret_cast<const uint2*>(                              \
                Bb + (wn * 64 + nj * 8 + grp) * BP + ks * 16 + qid * 4);           \
        _Pragma("unroll")                                                          \
        for (int mi = 0; mi < 4; mi++)                                             \
        _Pragma("unroll")                                                          \
        for (int nj = 0; nj < 8; nj++)                                             \
            mma_f16(acc[mi][nj], alo[mi], ahi[mi], bf[nj]);                        \
    }                                                                              \
} while (0)

    ISSUE(0, 0);
#pragma unroll 1
    for (int kt = 0; kt < NKT; kt++) {
        if (kt < NKT - 1) {
            ISSUE(kt + 1, (kt + 1) & 1);
            cp_wait<1>();
        } else {
            cp_wait<0>();
        }
        __syncthreads();
        COMPUTE(kt & 1);
        __syncthreads();
    }

    // ---- Epilogue: dump Z to smem, run the GRU recurrence over t ----
    float* Zs = (float*)smem;   // [128][ZPITCH]
#pragma unroll
    for (int mi = 0; mi < 4; mi++)
#pragma unroll
        for (int nj = 0; nj < 8; nj++)
#pragma unroll
            for (int r = 0; r < 4; r++) {
                int row = wm * 64 + mi * 16 + grp + ((r >> 1) ? 8 : 0);
                int col = wn * 64 + nj * 8 + qid * 2 + (r & 1);
                Zs[row * ZPITCH + col] = acc[mi][nj][r];
            }
    __syncthreads();

    {
        const int row = tid & 127;
        const int ul  = tid >> 7;
        const int n   = mt * 128 + row;
        const int u   = nt * 2 + ul;
        float h = h0[(size_t)u * NN + n];
        const float buv = bu[u];
        const float bcv = bc[u];
        const float* zrow = Zs + row * ZPITCH + ul * 128;
#pragma unroll 1
        for (int t = 0; t < NS; t++) {
            float zu = zrow[2 * t]     + buv;
            float zc = zrow[2 * t + 1] + bcv;
            float ug = 1.f / (1.f + __expf(-zu));
            float cg = tanhf(zc);
            h = fmaf(ug, h - cg, cg);
        }
        g_h[((size_t)b * NN + n) * NH + u] = h;
    }
#undef ISSUE
#undef COMPUTE
}

// ---------------- prediction head (R2 version, smem-transposed weights) ----------------
#define W1T_PITCH 33
__global__ void __launch_bounds__(256)
head_kernel(const float* __restrict__ W1, const float* __restrict__ b1,
            const float* __restrict__ W2, const float* __restrict__ b2,
            const float* __restrict__ Wd, const float* __restrict__ bd,
            float* __restrict__ out)
{
    __shared__ float w1t[NH * W1T_PITCH];
    __shared__ float w2t[2 * NH * W1T_PITCH];
    __shared__ float b1s[NH], b2s[NH];

    const int tid = threadIdx.x;
    for (int i = tid; i < NH * NH; i += 256) {
        int u = i >> 5, k = i & 31;
        w1t[k * W1T_PITCH + u] = W1[i];
    }
    for (int i = tid; i < NH * 2 * NH; i += 256) {
        int u = i >> 6, k = i & 63;
        w2t[k * W1T_PITCH + u] = W2[i];
    }
    if (tid < NH) { b1s[tid] = b1[tid]; b2s[tid] = b2[tid]; }
    __syncthreads();

    const int warp = (blockIdx.x * blockDim.x + tid) >> 5;
    const int lane = tid & 31;
    if (warp >= NB * NN) return;
    const int b = warp >> 10;
    const int n = warp & (NN - 1);

    const float hv = g_h[((size_t)b * NN + n) * NH + lane];

    float x1 = b1s[lane];
#pragma unroll
    for (int k = 0; k < NH; k++)
        x1 = fmaf(w1t[k * W1T_PITCH + lane], __shfl_sync(0xffffffffu, hv, k), x1);
    x1 = x1 >= 0.f ? x1 : 0.01f * x1;

    float x2 = b2s[lane];
#pragma unroll
    for (int k = 0; k < NH; k++)
        x2 = fmaf(w2t[k * W1T_PITCH + lane], __shfl_sync(0xffffffffu, x1, k), x2);
#pragma unroll
    for (int k = 0; k < NH; k++)
        x2 = fmaf(w2t[(NH + k) * W1T_PITCH + lane], __shfl_sync(0xffffffffu, hv, k), x2);
    x2 = x2 >= 0.f ? x2 : 0.01f * x2;

    float v = Wd[(size_t)n * 2 * NH + lane] * x2
            + Wd[(size_t)n * 2 * NH + NH + lane] * hv;
#pragma unroll
    for (int o = 16; o; o >>= 1) v += __shfl_xor_sync(0xffffffffu, v, o);
    if (lane == 0) out[(size_t)b * NN + n] = v + bd[n];
}

extern "C" void kernel_launch(void* const* d_in, const int* in_sizes, int n_in,
                              void* d_out, int out_size)
{
    (void)in_sizes; (void)n_in; (void)out_size;
    const float* x  = (const float*)d_in[0];
    const float* g  = (const float*)d_in[2];
    const float* Wu = (const float*)d_in[5];
    const float* bu = (const float*)d_in[6];
    const float* Wc = (const float*)d_in[7];
    const float* bc = (const float*)d_in[8];
    const float* h0 = (const float*)d_in[9];
    const float* W1 = (const float*)d_in[10];
    const float* b1 = (const float*)d_in[11];
    const float* W2 = (const float*)d_in[12];
    const float* b2 = (const float*)d_in[13];
    const float* Wd = (const float*)d_in[14];
    const float* bd = (const float*)d_in[15];
    float* out = (float*)d_out;

    convA_kernel<<<8192, 256>>>(g);
    convB_kernel<<<32768, 256>>>(x, Wu, Wc);

    cudaFuncSetAttribute(gemm_gru_kernel,
                         cudaFuncAttributeMaxDynamicSharedMemorySize, SMEM_BYTES);
    dim3 grid(8, 16, NB);   // 1024 CTAs
    gemm_gru_kernel<<<grid, 256, SMEM_BYTES>>>(bu, bc, h0);

    head_kernel<<<(NB * NN) / 8, 256>>>(W1, b1, W2, b2, Wd, bd, out);
}

// round 5
// speedup vs baseline: 2.5915x; 1.1584x over previous
#include <cuda_runtime.h>
#include <cuda_fp16.h>
#include <cstdint>

// Problem constants
#define NN 1024   // nodes
#define NB 8      // batch
#define NS 64     // timesteps
#define NH 32     // hidden

// GEMM tiling: per CTA, M=128 (n rows) x N=256 cols (2u x 64t x 2 gates), K=1024
#define BK 64
#define NKT 16           // k-iters
#define AP 80            // halfs per A row (64 data + 16 pad) -> conflict-free LDS.64
#define BP 80            // halfs per B col
#define ACHUNK (128 * AP)   // 10240 halfs per (tile, kchunk)
#define BCHUNK (256 * BP)   // 20480
#define ABYTES (ACHUNK * 2) // 20480 B
#define BBYTES (BCHUNK * 2) // 40960 B
#define ZPITCH 257
#define SMEM_BYTES (128 * ZPITCH * 4)   // 131584; staging (122880) aliases this

// Precomputed operand buffers
__device__ __half g_A[(size_t)NB * 8 * NKT * ACHUNK];    // ~21 MB, fragment-permuted
__device__ __half g_B[(size_t)NB * 16 * NKT * BCHUNK];   // ~84 MB, fragment-permuted
__device__ __half2 g_xh[(size_t)NB * NS * (NN / 2)];     // xh[b][t][m/2]  (transposed X)
__device__ __half2 g_wh[2 * NH * (NN / 2)];              // wh[gate*32+u][m/2]
__device__ float  g_h[NB * NN * NH];

// ---------------- helpers ----------------
__device__ __forceinline__ uint32_t smem_u32(const void* p) {
    uint32_t a;
    asm("{ .reg .u64 t; cvta.to.shared.u64 t, %1; cvt.u32.u64 %0, t; }" : "=r"(a) : "l"(p));
    return a;
}
__device__ __forceinline__ void cp16(uint32_t s, const void* g) {
    asm volatile("cp.async.cg.shared.global [%0], [%1], 16;" :: "r"(s), "l"(g) : "memory");
}
__device__ __forceinline__ void cp_commit() {
    asm volatile("cp.async.commit_group;" ::: "memory");
}
template <int N>
__device__ __forceinline__ void cp_wait() {
    asm volatile("cp.async.wait_group %0;" :: "n"(N) : "memory");
}
__device__ __forceinline__ void mma_f16(float c[4], uint2 alo, uint2 ahi, uint2 bf) {
    asm volatile(
        "mma.sync.aligned.m16n8k16.row.col.f32.f16.f16.f32 "
        "{%0,%1,%2,%3}, {%4,%5,%6,%7}, {%8,%9}, {%0,%1,%2,%3};\n"
        : "+f"(c[0]), "+f"(c[1]), "+f"(c[2]), "+f"(c[3])
        : "r"(alo.x), "r"(ahi.x), "r"(alo.y), "r"(ahi.y), "r"(bf.x), "r"(bf.y));
}
__device__ __forceinline__ uint32_t pack2(float a, float b) {
    __half2 h = __halves2half2(__float2half_rn(a), __float2half_rn(b));
    return *reinterpret_cast<uint32_t*>(&h);
}

// ---------------- prep: A = half(G), fragment-permuted ----------------
__global__ void convA_kernel(const float* __restrict__ G) {
    int idx = blockIdx.x * 256 + threadIdx.x;   // 2,097,152 quads
    int q   = idx & 3;
    int ks  = (idx >> 2) & 3;
    int row = (idx >> 4) & 127;
    int kt  = (idx >> 11) & 15;
    int mt  = (idx >> 15) & 7;
    int b   = idx >> 18;
    const float* src = G + ((size_t)b * NN + mt * 128 + row) * NN + kt * 64 + ks * 16 + 2 * q;
    uint2 v;
    v.x = pack2(src[0], src[1]);
    v.y = pack2(src[8], src[9]);
    *reinterpret_cast<uint2*>(
        g_A + (size_t)((b * 8 + mt) * 16 + kt) * ACHUNK + row * AP + ks * 16 + q * 4) = v;
}

// ---------------- prep: xh[b][t][m/2] ----------------
__global__ void xh_kernel(const float* __restrict__ X) {
    int idx = blockIdx.x * 256 + threadIdx.x;   // 262,144
    int m2 = idx & 511;
    int t  = (idx >> 9) & 63;
    int b  = idx >> 15;
    const float* src = X + (size_t)b * NN * NS + (size_t)(2 * m2) * NS + t;
    g_xh[(size_t)(b * NS + t) * 512 + m2] =
        __halves2half2(__float2half_rn(src[0]), __float2half_rn(src[NS]));
}

// ---------------- prep: wh[gate*32+u][m/2] ----------------
__global__ void wh_kernel(const float* __restrict__ Wu, const float* __restrict__ Wc) {
    int idx = blockIdx.x * 256 + threadIdx.x;   // 32,768
    int m2 = idx & 511;
    int u  = (idx >> 9) & 31;
    int gate = idx >> 14;
    const float* src = (gate ? Wc : Wu) + (size_t)u * NN + 2 * m2;
    g_wh[(size_t)(gate * NH + u) * 512 + m2] =
        __halves2half2(__float2half_rn(src[0]), __float2half_rn(src[1]));
}

// ---------------- prep: B[col,k] = wh[u_g,k]*xh[t,k], fragment-permuted ----------------
__global__ void convB2_kernel() {
    int idx = blockIdx.x * 256 + threadIdx.x;   // 2,097,152
    int ks  = idx & 3;
    int col = (idx >> 2) & 255;
    int kt  = (idx >> 10) & 15;
    int nt  = (idx >> 14) & 15;
    int b   = idx >> 18;
    int ul = col >> 7, t = (col & 127) >> 1, gate = col & 1;
    int u  = nt * 2 + ul;

    const __half2* xp = g_xh + (size_t)(b * NS + t) * 512 + kt * 32 + ks * 8;
    const __half2* wp = g_wh + (size_t)(gate * NH + u) * 512 + kt * 32 + ks * 8;

    uint32_t r[8];
#pragma unroll
    for (int j = 0; j < 8; j++) {
        __half2 v = __hmul2(wp[j], xp[j]);
        r[j] = *reinterpret_cast<uint32_t*>(&v);
    }
    uint4 o0 = make_uint4(r[0], r[4], r[1], r[5]);
    uint4 o1 = make_uint4(r[2], r[6], r[3], r[7]);
    uint4* dst = reinterpret_cast<uint4*>(
        g_B + (size_t)((b * 16 + nt) * 16 + kt) * BCHUNK + col * BP + ks * 16);
    dst[0] = o0;
    dst[1] = o1;
}

// ---------------- main: fp16 HMMA GEMM + fused GRU scan ----------------
__global__ void __launch_bounds__(256, 1)
gemm_gru_kernel(const float* __restrict__ bu, const float* __restrict__ bc,
                const float* __restrict__ h0)
{
    extern __shared__ __align__(16) char smem[];
    const uint32_t sb = smem_u32(smem);

    const int tid  = threadIdx.x;
    const int wid  = tid >> 5;
    const int lane = tid & 31;
    const int wm   = wid >> 2;
    const int wn   = wid & 3;
    const int grp  = lane >> 2;
    const int qid  = lane & 3;

    const int mt = blockIdx.x;
    const int nt = blockIdx.y;
    const int b  = blockIdx.z;

    const __half* Asrc = g_A + (size_t)((b * 8 + mt) * 16) * ACHUNK;
    const __half* Bsrc = g_B + (size_t)((b * 16 + nt) * 16) * BCHUNK;

    float acc[4][8][4];
#pragma unroll
    for (int i = 0; i < 4; i++)
#pragma unroll
        for (int j = 0; j < 8; j++)
#pragma unroll
            for (int r = 0; r < 4; r++) acc[i][j][r] = 0.f;

#define ISSUE(KT, BUF) do {                                                        \
    uint32_t sa = sb + (BUF) * ABYTES;                                             \
    const char* ga = (const char*)(Asrc + (size_t)(KT) * ACHUNK);                  \
    _Pragma("unroll")                                                              \
    for (int i = 0; i < 5; i++)                                                    \
        cp16(sa + tid * 16 + i * 4096, ga + tid * 16 + i * 4096);                  \
    uint32_t sB = sb + 2 * ABYTES + (BUF) * BBYTES;                                \
    const char* gb = (const char*)(Bsrc + (size_t)(KT) * BCHUNK);                  \
    _Pragma("unroll")                                                              \
    for (int i = 0; i < 10; i++)                                                   \
        cp16(sB + tid * 16 + i * 4096, gb + tid * 16 + i * 4096);                  \
    cp_commit();                                                                   \
} while (0)

#define COMPUTE(BUF) do {                                                          \
    const __half* Ab = (const __half*)(smem + (BUF) * ABYTES);                     \
    const __half* Bb = (const __half*)(smem + 2 * ABYTES + (BUF) * BBYTES);        \
    _Pragma("unroll")                                                              \
    for (int ks = 0; ks < 4; ks++) {                                               \
        uint2 alo[4], ahi[4], bf[8];                                               \
        _Pragma("unroll")                                                          \
        for (int mi = 0; mi < 4; mi++) {                                           \
            const __half* ap = Ab + (wm * 64 + mi * 16 + grp) * AP + ks * 16 + qid * 4; \
            alo[mi] = *reinterpret_cast<const uint2*>(ap);                         \
            ahi[mi] = *reinterpret_cast<const uint2*>(ap + 8 * AP);                \
        }                                                                          \
        _Pragma("unroll")                                                          \
        for (int nj = 0; nj < 8; nj++)                                             \
            bf[nj] = *reinterpret_cast<const uint2*>(                              \
                Bb + (wn * 64 + nj * 8 + grp) * BP + ks * 16 + qid * 4);           \
        _Pragma("unroll")                                                          \
        for (int mi = 0; mi < 4; mi++)                                             \
        _Pragma("unroll")                                                          \
        for (int nj = 0; nj < 8; nj++)                                             \
            mma_f16(acc[mi][nj], alo[mi], ahi[mi], bf[nj]);                        \
    }                                                                              \
} while (0)

    ISSUE(0, 0);
#pragma unroll 1
    for (int kt = 0; kt < NKT; kt++) {
        if (kt < NKT - 1) {
            ISSUE(kt + 1, (kt + 1) & 1);
            cp_wait<1>();
        } else {
            cp_wait<0>();
        }
        __syncthreads();
        COMPUTE(kt & 1);
        __syncthreads();
    }

    float* Zs = (float*)smem;   // [128][ZPITCH]
#pragma unroll
    for (int mi = 0; mi < 4; mi++)
#pragma unroll
        for (int nj = 0; nj < 8; nj++)
#pragma unroll
            for (int r = 0; r < 4; r++) {
                int row = wm * 64 + mi * 16 + grp + ((r >> 1) ? 8 : 0);
                int col = wn * 64 + nj * 8 + qid * 2 + (r & 1);
                Zs[row * ZPITCH + col] = acc[mi][nj][r];
            }
    __syncthreads();

    {
        const int row = tid & 127;
        const int ul  = tid >> 7;
        const int n   = mt * 128 + row;
        const int u   = nt * 2 + ul;
        float h = h0[(size_t)u * NN + n];
        const float buv = bu[u];
        const float bcv = bc[u];
        const float* zrow = Zs + row * ZPITCH + ul * 128;
#pragma unroll 1
        for (int t = 0; t < NS; t++) {
            float zu = zrow[2 * t]     + buv;
            float zc = zrow[2 * t + 1] + bcv;
            float ug = 1.f / (1.f + __expf(-zu));
            float cg = tanhf(zc);
            h = fmaf(ug, h - cg, cg);
        }
        g_h[((size_t)b * NN + n) * NH + u] = h;
    }
#undef ISSUE
#undef COMPUTE
}

// ---------------- prediction head ----------------
#define W1T_PITCH 33
__global__ void __launch_bounds__(256)
head_kernel(const float* __restrict__ W1, const float* __restrict__ b1,
            const float* __restrict__ W2, const float* __restrict__ b2,
            const float* __restrict__ Wd, const float* __restrict__ bd,
            float* __restrict__ out)
{
    __shared__ float w1t[NH * W1T_PITCH];
    __shared__ float w2t[2 * NH * W1T_PITCH];
    __shared__ float b1s[NH], b2s[NH];

    const int tid = threadIdx.x;
    for (int i = tid; i < NH * NH; i += 256) {
        int u = i >> 5, k = i & 31;
        w1t[k * W1T_PITCH + u] = W1[i];
    }
    for (int i = tid; i < NH * 2 * NH; i += 256) {
        int u = i >> 6, k = i & 63;
        w2t[k * W1T_PITCH + u] = W2[i];
    }
    if (tid < NH) { b1s[tid] = b1[tid]; b2s[tid] = b2[tid]; }
    __syncthreads();

    const int warp = (blockIdx.x * blockDim.x + tid) >> 5;
    const int lane = tid & 31;
    if (warp >= NB * NN) return;
    const int b = warp >> 10;
    const int n = warp & (NN - 1);

    const float hv = g_h[((size_t)b * NN + n) * NH + lane];

    float p0 = 0.f, p1 = 0.f, p2 = 0.f, p3 = 0.f;
#pragma unroll
    for (int k = 0; k < NH; k += 4) {
        p0 = fmaf(w1t[(k + 0) * W1T_PITCH + lane], __shfl_sync(0xffffffffu, hv, k + 0), p0);
        p1 = fmaf(w1t[(k + 1) * W1T_PITCH + lane], __shfl_sync(0xffffffffu, hv, k + 1), p1);
        p2 = fmaf(w1t[(k + 2) * W1T_PITCH + lane], __shfl_sync(0xffffffffu, hv, k + 2), p2);
        p3 = fmaf(w1t[(k + 3) * W1T_PITCH + lane], __shfl_sync(0xffffffffu, hv, k + 3), p3);
    }
    float x1 = b1s[lane] + ((p0 + p1) + (p2 + p3));
    x1 = x1 >= 0.f ? x1 : 0.01f * x1;

    float q0 = 0.f, q1 = 0.f, q2 = 0.f, q3 = 0.f;
#pragma unroll
    for (int k = 0; k < NH; k += 4) {
        q0 = fmaf(w2t[(k + 0) * W1T_PITCH + lane], __shfl_sync(0xffffffffu, x1, k + 0), q0);
        q1 = fmaf(w2t[(k + 1) * W1T_PITCH + lane], __shfl_sync(0xffffffffu, x1, k + 1), q1);
        q2 = fmaf(w2t[(k + 2) * W1T_PITCH + lane], __shfl_sync(0xffffffffu, x1, k + 2), q2);
        q3 = fmaf(w2t[(k + 3) * W1T_PITCH + lane], __shfl_sync(0xffffffffu, x1, k + 3), q3);
    }
#pragma unroll
    for (int k = 0; k < NH; k += 4) {
        q0 = fmaf(w2t[(NH + k + 0) * W1T_PITCH + lane], __shfl_sync(0xffffffffu, hv, k + 0), q0);
        q1 = fmaf(w2t[(NH + k + 1) * W1T_PITCH + lane], __shfl_sync(0xffffffffu, hv, k + 1), q1);
        q2 = fmaf(w2t[(NH + k + 2) * W1T_PITCH + lane], __shfl_sync(0xffffffffu, hv, k + 2), q2);
        q3 = fmaf(w2t[(NH + k + 3) * W1T_PITCH + lane], __shfl_sync(0xffffffffu, hv, k + 3), q3);
    }
    float x2 = b2s[lane] + ((q0 + q1) + (q2 + q3));
    x2 = x2 >= 0.f ? x2 : 0.01f * x2;

    float v = Wd[(size_t)n * 2 * NH + lane] * x2
            + Wd[(size_t)n * 2 * NH + NH + lane] * hv;
#pragma unroll
    for (int o = 16; o; o >>= 1) v += __shfl_xor_sync(0xffffffffu, v, o);
    if (lane == 0) out[(size_t)b * NN + n] = v + bd[n];
}

extern "C" void kernel_launch(void* const* d_in, const int* in_sizes, int n_in,
                              void* d_out, int out_size)
{
    (void)in_sizes; (void)n_in; (void)out_size;
    const float* x  = (const float*)d_in[0];
    const float* g  = (const float*)d_in[2];
    const float* Wu = (const float*)d_in[5];
    const float* bu = (const float*)d_in[6];
    const float* Wc = (const float*)d_in[7];
    const float* bc = (const float*)d_in[8];
    const float* h0 = (const float*)d_in[9];
    const float* W1 = (const float*)d_in[10];
    const float* b1 = (const float*)d_in[11];
    const float* W2 = (const float*)d_in[12];
    const float* b2 = (const float*)d_in[13];
    const float* Wd = (const float*)d_in[14];
    const float* bd = (const float*)d_in[15];
    float* out = (float*)d_out;

    convA_kernel<<<8192, 256>>>(g);
    xh_kernel<<<1024, 256>>>(x);
    wh_kernel<<<128, 256>>>(Wu, Wc);
    convB2_kernel<<<8192, 256>>>();

    cudaFuncSetAttribute(gemm_gru_kernel,
                         cudaFuncAttributeMaxDynamicSharedMemorySize, SMEM_BYTES);
    dim3 grid(8, 16, NB);
    gemm_gru_kernel<<<grid, 256, SMEM_BYTES>>>(bu, bc, h0);

    head_kernel<<<(NB * NN) / 8, 256>>>(W1, b1, W2, b2, Wd, bd, out);
}

// round 6
// speedup vs baseline: 2.6093x; 1.0069x over previous
#include <cuda_runtime.h>
#include <cuda_fp16.h>
#include <cstdint>

// Problem constants
#define NN 1024   // nodes
#define NB 8      // batch
#define NS 64     // timesteps
#define NH 32     // hidden

// GEMM tiling: per CTA, M=128 (n rows) x N=256 cols (2u x 64t x 2 gates), K=1024
#define BK 64
#define NKT 16           // k-iters
#define STAGES 3
#define AP 80            // halfs per A row (64 data + 16 pad) -> conflict-free LDS.64
#define BP 80            // halfs per B col
#define ACHUNK (128 * AP)   // 10240 halfs per (tile, kchunk)
#define BCHUNK (256 * BP)   // 20480
#define ABYTES (ACHUNK * 2) // 20480 B
#define BBYTES (BCHUNK * 2) // 40960 B
#define SBYTES (ABYTES + BBYTES)        // 61440 per stage
#define ZPITCH 257
#define SMEM_BYTES (STAGES * SBYTES)    // 184320; Z tile (131584) aliases this

// Precomputed operand buffers
__device__ __half g_A[(size_t)NB * 8 * NKT * ACHUNK];    // ~21 MB, fragment-permuted
__device__ __half g_B[(size_t)NB * 16 * NKT * BCHUNK];   // ~84 MB, fragment-permuted
__device__ __half2 g_xh[(size_t)NB * NS * (NN / 2)];     // xh[b][t][m/2]
__device__ __half2 g_wh[2 * NH * (NN / 2)];              // wh[gate*32+u][m/2]
__device__ float  g_h[NB * NN * NH];

// ---------------- helpers ----------------
__device__ __forceinline__ uint32_t smem_u32(const void* p) {
    uint32_t a;
    asm("{ .reg .u64 t; cvta.to.shared.u64 t, %1; cvt.u32.u64 %0, t; }" : "=r"(a) : "l"(p));
    return a;
}
__device__ __forceinline__ void cp16(uint32_t s, const void* g) {
    asm volatile("cp.async.cg.shared.global [%0], [%1], 16;" :: "r"(s), "l"(g) : "memory");
}
__device__ __forceinline__ void cp_commit() {
    asm volatile("cp.async.commit_group;" ::: "memory");
}
template <int N>
__device__ __forceinline__ void cp_wait() {
    asm volatile("cp.async.wait_group %0;" :: "n"(N) : "memory");
}
__device__ __forceinline__ void mma_f16(float c[4], uint2 alo, uint2 ahi, uint2 bf) {
    asm volatile(
        "mma.sync.aligned.m16n8k16.row.col.f32.f16.f16.f32 "
        "{%0,%1,%2,%3}, {%4,%5,%6,%7}, {%8,%9}, {%0,%1,%2,%3};\n"
        : "+f"(c[0]), "+f"(c[1]), "+f"(c[2]), "+f"(c[3])
        : "r"(alo.x), "r"(ahi.x), "r"(alo.y), "r"(ahi.y), "r"(bf.x), "r"(bf.y));
}
__device__ __forceinline__ uint32_t pack2(float a, float b) {
    __half2 h = __halves2half2(__float2half_rn(a), __float2half_rn(b));
    return *reinterpret_cast<uint32_t*>(&h);
}

// ---------------- prep: A = half(G), fragment-permuted ----------------
__global__ void convA_kernel(const float* __restrict__ G) {
    int idx = blockIdx.x * 256 + threadIdx.x;   // 2,097,152 quads
    int q   = idx & 3;
    int ks  = (idx >> 2) & 3;
    int row = (idx >> 4) & 127;
    int kt  = (idx >> 11) & 15;
    int mt  = (idx >> 15) & 7;
    int b   = idx >> 18;
    const float* src = G + ((size_t)b * NN + mt * 128 + row) * NN + kt * 64 + ks * 16 + 2 * q;
    uint2 v;
    v.x = pack2(src[0], src[1]);
    v.y = pack2(src[8], src[9]);
    *reinterpret_cast<uint2*>(
        g_A + (size_t)((b * 8 + mt) * 16 + kt) * ACHUNK + row * AP + ks * 16 + q * 4) = v;
}

// ---------------- prep: xh[b][t][m/2] ----------------
__global__ void xh_kernel(const float* __restrict__ X) {
    int idx = blockIdx.x * 256 + threadIdx.x;   // 262,144
    int m2 = idx & 511;
    int t  = (idx >> 9) & 63;
    int b  = idx >> 15;
    const float* src = X + (size_t)b * NN * NS + (size_t)(2 * m2) * NS + t;
    g_xh[(size_t)(b * NS + t) * 512 + m2] =
        __halves2half2(__float2half_rn(src[0]), __float2half_rn(src[NS]));
}

// ---------------- prep: wh[gate*32+u][m/2] ----------------
__global__ void wh_kernel(const float* __restrict__ Wu, const float* __restrict__ Wc) {
    int idx = blockIdx.x * 256 + threadIdx.x;   // 32,768
    int m2 = idx & 511;
    int u  = (idx >> 9) & 31;
    int gate = idx >> 14;
    const float* src = (gate ? Wc : Wu) + (size_t)u * NN + 2 * m2;
    g_wh[(size_t)(gate * NH + u) * 512 + m2] =
        __halves2half2(__float2half_rn(src[0]), __float2half_rn(src[1]));
}

// ---------------- prep: B[col,k] = wh[u_g,k]*xh[t,k], fragment-permuted ----------------
__global__ void convB2_kernel() {
    int idx = blockIdx.x * 256 + threadIdx.x;   // 2,097,152
    int ks  = idx & 3;
    int col = (idx >> 2) & 255;
    int kt  = (idx >> 10) & 15;
    int nt  = (idx >> 14) & 15;
    int b   = idx >> 18;
    int ul = col >> 7, t = (col & 127) >> 1, gate = col & 1;
    int u  = nt * 2 + ul;

    const __half2* xp = g_xh + (size_t)(b * NS + t) * 512 + kt * 32 + ks * 8;
    const __half2* wp = g_wh + (size_t)(gate * NH + u) * 512 + kt * 32 + ks * 8;

    uint32_t r[8];
#pragma unroll
    for (int j = 0; j < 8; j++) {
        __half2 v = __hmul2(wp[j], xp[j]);
        r[j] = *reinterpret_cast<uint32_t*>(&v);
    }
    uint4 o0 = make_uint4(r[0], r[4], r[1], r[5]);
    uint4 o1 = make_uint4(r[2], r[6], r[3], r[7]);
    uint4* dst = reinterpret_cast<uint4*>(
        g_B + (size_t)((b * 16 + nt) * 16 + kt) * BCHUNK + col * BP + ks * 16);
    dst[0] = o0;
    dst[1] = o1;
}

// ---------------- main: fp16 HMMA GEMM (3-stage cp.async ring) + fused GRU ----------------
__global__ void __launch_bounds__(256, 1)
gemm_gru_kernel(const float* __restrict__ bu, const float* __restrict__ bc,
                const float* __restrict__ h0)
{
    extern __shared__ __align__(16) char smem[];
    const uint32_t sb = smem_u32(smem);

    const int tid  = threadIdx.x;
    const int wid  = tid >> 5;
    const int lane = tid & 31;
    const int wm   = wid >> 2;
    const int wn   = wid & 3;
    const int grp  = lane >> 2;
    const int qid  = lane & 3;

    const int mt = blockIdx.x;
    const int nt = blockIdx.y;
    const int b  = blockIdx.z;

    const __half* Asrc = g_A + (size_t)((b * 8 + mt) * 16) * ACHUNK;
    const __half* Bsrc = g_B + (size_t)((b * 16 + nt) * 16) * BCHUNK;

    float acc[4][8][4];
#pragma unroll
    for (int i = 0; i < 4; i++)
#pragma unroll
        for (int j = 0; j < 8; j++)
#pragma unroll
            for (int r = 0; r < 4; r++) acc[i][j][r] = 0.f;

#define ISSUE(KT, SLOT) do {                                                       \
    uint32_t sa = sb + (SLOT) * SBYTES;                                            \
    const char* ga = (const char*)(Asrc + (size_t)(KT) * ACHUNK);                  \
    _Pragma("unroll")                                                              \
    for (int i = 0; i < 5; i++)                                                    \
        cp16(sa + tid * 16 + i * 4096, ga + tid * 16 + i * 4096);                  \
    uint32_t sB = sa + ABYTES;                                                     \
    const char* gb = (const char*)(Bsrc + (size_t)(KT) * BCHUNK);                  \
    _Pragma("unroll")                                                              \
    for (int i = 0; i < 10; i++)                                                   \
        cp16(sB + tid * 16 + i * 4096, gb + tid * 16 + i * 4096);                  \
    cp_commit();                                                                   \
} while (0)

#define COMPUTE(SLOT) do {                                                         \
    const __half* Ab = (const __half*)(smem + (SLOT) * SBYTES);                    \
    const __half* Bb = (const __half*)(smem + (SLOT) * SBYTES + ABYTES);           \
    _Pragma("unroll")                                                              \
    for (int ks = 0; ks < 4; ks++) {                                               \
        uint2 alo[4], ahi[4], bf[8];                                               \
        _Pragma("unroll")                                                          \
        for (int mi = 0; mi < 4; mi++) {                                           \
            const __half* ap = Ab + (wm * 64 + mi * 16 + grp) * AP + ks * 16 + qid * 4; \
            alo[mi] = *reinterpret_cast<const uint2*>(ap);                         \
            ahi[mi] = *reinterpret_cast<const uint2*>(ap + 8 * AP);                \
        }                                                                          \
        _Pragma("unroll")                                                          \
        for (int nj = 0; nj < 8; nj++)                                             \
            bf[nj] = *reinterpret_cast<const uint2*>(                              \
                Bb + (wn * 64 + nj * 8 + grp) * BP + ks * 16 + qid * 4);           \
        _Pragma("unroll")                                                          \
        for (int mi = 0; mi < 4; mi++)                                             \
        _Pragma("unroll")                                                          \
        for (int nj = 0; nj < 8; nj++)                                             \
            mma_f16(acc[mi][nj], alo[mi], ahi[mi], bf[nj]);                        \
    }                                                                              \
} while (0)

    // Prologue: stages 0 and 1 in flight
    ISSUE(0, 0);
    ISSUE(1, 1);

    int slot = 0;
#pragma unroll 1
    for (int kt = 0; kt < NKT; kt++) {
        if (kt < NKT - 1) cp_wait<1>();   // stage kt landed (kt+1 may still fly)
        else              cp_wait<0>();   // last stage: nothing else outstanding
        __syncthreads();                  // publish stage kt; license slot reuse
        if (kt + 2 < NKT) {
            int ns = slot + 2; if (ns >= STAGES) ns -= STAGES;
            ISSUE(kt + 2, ns);            // overwrites slot of kt-1 (sync passed)
        }
        COMPUTE(slot);
        if (++slot == STAGES) slot = 0;
    }
    __syncthreads();   // all COMPUTE done before Z aliases staging smem

    // ---- Epilogue: dump Z to smem, run the GRU recurrence over t ----
    float* Zs = (float*)smem;   // [128][ZPITCH]
#pragma unroll
    for (int mi = 0; mi < 4; mi++)
#pragma unroll
        for (int nj = 0; nj < 8; nj++)
#pragma unroll
            for (int r = 0; r < 4; r++) {
                int row = wm * 64 + mi * 16 + grp + ((r >> 1) ? 8 : 0);
                int col = wn * 64 + nj * 8 + qid * 2 + (r & 1);
                Zs[row * ZPITCH + col] = acc[mi][nj][r];
            }
    __syncthreads();

    {
        const int row = tid & 127;
        const int ul  = tid >> 7;
        const int n   = mt * 128 + row;
        const int u   = nt * 2 + ul;
        float h = h0[(size_t)u * NN + n];
        const float buv = bu[u];
        const float bcv = bc[u];
        const float* zrow = Zs + row * ZPITCH + ul * 128;
#pragma unroll 1
        for (int t = 0; t < NS; t++) {
            float zu = zrow[2 * t]     + buv;
            float zc = zrow[2 * t + 1] + bcv;
            float ug = 1.f / (1.f + __expf(-zu));
            float cg = tanhf(zc);
            h = fmaf(ug, h - cg, cg);
        }
        g_h[((size_t)b * NN + n) * NH + u] = h;
    }
#undef ISSUE
#undef COMPUTE
}

// ---------------- prediction head ----------------
#define W1T_PITCH 33
__global__ void __launch_bounds__(256)
head_kernel(const float* __restrict__ W1, const float* __restrict__ b1,
            const float* __restrict__ W2, const float* __restrict__ b2,
            const float* __restrict__ Wd, const float* __restrict__ bd,
            float* __restrict__ out)
{
    __shared__ float w1t[NH * W1T_PITCH];
    __shared__ float w2t[2 * NH * W1T_PITCH];
    __shared__ float b1s[NH], b2s[NH];

    const int tid = threadIdx.x;
    for (int i = tid; i < NH * NH; i += 256) {
        int u = i >> 5, k = i & 31;
        w1t[k * W1T_PITCH + u] = W1[i];
    }
    for (int i = tid; i < NH * 2 * NH; i += 256) {
        int u = i >> 6, k = i & 63;
        w2t[k * W1T_PITCH + u] = W2[i];
    }
    if (tid < NH) { b1s[tid] = b1[tid]; b2s[tid] = b2[tid]; }
    __syncthreads();

    const int warp = (blockIdx.x * blockDim.x + tid) >> 5;
    const int lane = tid & 31;
    if (warp >= NB * NN) return;
    const int b = warp >> 10;
    const int n = warp & (NN - 1);

    const float hv = g_h[((size_t)b * NN + n) * NH + lane];

    float p0 = 0.f, p1 = 0.f, p2 = 0.f, p3 = 0.f;
#pragma unroll
    for (int k = 0; k < NH; k += 4) {
        p0 = fmaf(w1t[(k + 0) * W1T_PITCH + lane], __shfl_sync(0xffffffffu, hv, k + 0), p0);
        p1 = fmaf(w1t[(k + 1) * W1T_PITCH + lane], __shfl_sync(0xffffffffu, hv, k + 1), p1);
        p2 = fmaf(w1t[(k + 2) * W1T_PITCH + lane], __shfl_sync(0xffffffffu, hv, k + 2), p2);
        p3 = fmaf(w1t[(k + 3) * W1T_PITCH + lane], __shfl_sync(0xffffffffu, hv, k + 3), p3);
    }
    float x1 = b1s[lane] + ((p0 + p1) + (p2 + p3));
    x1 = x1 >= 0.f ? x1 : 0.01f * x1;

    float q0 = 0.f, q1 = 0.f, q2 = 0.f, q3 = 0.f;
#pragma unroll
    for (int k = 0; k < NH; k += 4) {
        q0 = fmaf(w2t[(k + 0) * W1T_PITCH + lane], __shfl_sync(0xffffffffu, x1, k + 0), q0);
        q1 = fmaf(w2t[(k + 1) * W1T_PITCH + lane], __shfl_sync(0xffffffffu, x1, k + 1), q1);
        q2 = fmaf(w2t[(k + 2) * W1T_PITCH + lane], __shfl_sync(0xffffffffu, x1, k + 2), q2);
        q3 = fmaf(w2t[(k + 3) * W1T_PITCH + lane], __shfl_sync(0xffffffffu, x1, k + 3), q3);
    }
#pragma unroll
    for (int k = 0; k < NH; k += 4) {
        q0 = fmaf(w2t[(NH + k + 0) * W1T_PITCH + lane], __shfl_sync(0xffffffffu, hv, k + 0), q0);
        q1 = fmaf(w2t[(NH + k + 1) * W1T_PITCH + lane], __shfl_sync(0xffffffffu, hv, k + 1), q1);
        q2 = fmaf(w2t[(NH + k + 2) * W1T_PITCH + lane], __shfl_sync(0xffffffffu, hv, k + 2), q2);
        q3 = fmaf(w2t[(NH + k + 3) * W1T_PITCH + lane], __shfl_sync(0xffffffffu, hv, k + 3), q3);
    }
    float x2 = b2s[lane] + ((q0 + q1) + (q2 + q3));
    x2 = x2 >= 0.f ? x2 : 0.01f * x2;

    float v = Wd[(size_t)n * 2 * NH + lane] * x2
            + Wd[(size_t)n * 2 * NH + NH + lane] * hv;
#pragma unroll
    for (int o = 16; o; o >>= 1) v += __shfl_xor_sync(0xffffffffu, v, o);
    if (lane == 0) out[(size_t)b * NN + n] = v + bd[n];
}

extern "C" void kernel_launch(void* const* d_in, const int* in_sizes, int n_in,
                              void* d_out, int out_size)
{
    (void)in_sizes; (void)n_in; (void)out_size;
    const float* x  = (const float*)d_in[0];
    const float* g  = (const float*)d_in[2];
    const float* Wu = (const float*)d_in[5];
    const float* bu = (const float*)d_in[6];
    const float* Wc = (const float*)d_in[7];
    const float* bc = (const float*)d_in[8];
    const float* h0 = (const float*)d_in[9];
    const float* W1 = (const float*)d_in[10];
    const float* b1 = (const float*)d_in[11];
    const float* W2 = (const float*)d_in[12];
    const float* b2 = (const float*)d_in[13];
    const float* Wd = (const float*)d_in[14];
    const float* bd = (const float*)d_in[15];
    float* out = (float*)d_out;

    convA_kernel<<<8192, 256>>>(g);
    xh_kernel<<<1024, 256>>>(x);
    wh_kernel<<<128, 256>>>(Wu, Wc);
    convB2_kernel<<<8192, 256>>>();

    cudaFuncSetAttribute(gemm_gru_kernel,
                         cudaFuncAttributeMaxDynamicSharedMemorySize, SMEM_BYTES);
    dim3 grid(8, 16, NB);
    gemm_gru_kernel<<<grid, 256, SMEM_BYTES>>>(bu, bc, h0);

    head_kernel<<<(NB * NN) / 8, 256>>>(W1, b1, W2, b2, Wd, bd, out);
}